// round 6
// baseline (speedup 1.0000x reference)
#include <cuda_runtime.h>
#include <math.h>

#define Bn 32
#define Qn 2000
#define Gn 64
#define Cn 80
#define LISTN 8

// Scratch
__device__ float g_costT[Bn * Gn * Qn];            // [b][g][q]
__device__ float g_iouT [Bn * Gn * Qn];            // [b][g][q]
__device__ int   g_gmin [Bn * Qn];                 // first argmin over g of cost row
__device__ int   g_list [Bn * Gn * LISTN];         // per-gt smallest-cost query ids, sorted (v,idx)
__device__ int   g_selk [Bn * Gn];                 // dynamic k per gt
__device__ unsigned long long g_match[Bn * Qn];    // final match bitmask per query

// ordered-float transforms (ascending order preserving)
__device__ __forceinline__ unsigned int ordf(float f) {
    unsigned int u = __float_as_uint(f);
    return (u & 0x80000000u) ? ~u : (u | 0x80000000u);
}
__device__ __forceinline__ float unordf(unsigned int o) {
    unsigned int u = (o & 0x80000000u) ? (o ^ 0x80000000u) : ~o;
    return __uint_as_float(u);
}

// ---------------------------------------------------------------------------
// Stage A: pairwise cost + iou + row argmin (per-g invariants hoisted to smem)
// ---------------------------------------------------------------------------
__global__ __launch_bounds__(128) void stageA(
        const float* __restrict__ logits,   // [B,Q,C]
        const float* __restrict__ boxes,    // [B,Q,4]
        const int*   __restrict__ gtcls,    // [B,G]
        const float* __restrict__ gtbox,    // [B,G,4]
        const float* __restrict__ szout,    // [B,4]
        const float* __restrict__ sztgt)    // [B,G,4]
{
    int b = blockIdx.x;

    __shared__ float s_gx1[Gn], s_gy1[Gn], s_gx2[Gn], s_gy2[Gn];
    __shared__ float s_areaB[Gn];
    __shared__ float s_bl[Gn], s_br[Gn], s_bt[Gn], s_bb[Gn];
    __shared__ float s_t0[Gn], s_t1[Gn], s_t2[Gn], s_t3[Gn];
    __shared__ int   s_cls[Gn];

    if (threadIdx.x < Gn) {
        int g = threadIdx.x;
        const float* gb = gtbox + (size_t)(b * Gn + g) * 4;
        float gx1 = gb[0], gy1 = gb[1], gx2 = gb[2], gy2 = gb[3];
        s_gx1[g] = gx1; s_gy1[g] = gy1; s_gx2[g] = gx2; s_gy2[g] = gy2;
        s_areaB[g] = (gx2 - gx1) * (gy2 - gy1);
        float gcx = (gx1 + gx2) * 0.5f, gcy = (gy1 + gy2) * 0.5f;
        float gw = gx2 - gx1, gh = gy2 - gy1;
        s_bl[g] = gcx - 2.5f * gw; s_br[g] = gcx + 2.5f * gw;
        s_bt[g] = gcy - 2.5f * gh; s_bb[g] = gcy + 2.5f * gh;
        const float* tz = sztgt + (size_t)(b * Gn + g) * 4;
        s_t0[g] = gx1 / tz[0]; s_t1[g] = gy1 / tz[1];
        s_t2[g] = gx2 / tz[2]; s_t3[g] = gy2 / tz[3];
        s_cls[g] = gtcls[b * Gn + g];
    }
    __syncthreads();

    int q = blockIdx.y * blockDim.x + threadIdx.x;
    if (q >= Qn) return;

    const float* bp = boxes + (size_t)(b * Qn + q) * 4;
    float x1 = bp[0], y1 = bp[1], x2 = bp[2], y2 = bp[3];
    float cx = (x1 + x2) * 0.5f, cy = (y1 + y2) * 0.5f;
    float areaA = (x2 - x1) * (y2 - y1);

    bool anyIB = false, anyIC = false;
    for (int g = 0; g < Gn; g++) {
        bool ib = (cx > s_gx1[g]) && (cx < s_gx2[g]) && (cy > s_gy1[g]) && (cy < s_gy2[g]);
        bool icf = (cx > s_bl[g]) && (cx < s_br[g]) && (cy > s_bt[g]) && (cy < s_bb[g]);
        anyIB |= ib; anyIC |= icf;
    }
    float fgpen = (anyIB || anyIC) ? 0.f : 1e4f;

    float so0 = szout[b * 4], so1 = szout[b * 4 + 1], so2 = szout[b * 4 + 2], so3 = szout[b * 4 + 3];
    float nx1 = x1 / so0, ny1 = y1 / so1, nx2 = x2 / so2, ny2 = y2 / so3;
    const float* lr = logits + (size_t)(b * Qn + q) * Cn;

    float* costOut = g_costT + (size_t)b * Gn * Qn;
    float* iouOut  = g_iouT  + (size_t)b * Gn * Qn;

    float best = 3.4e38f; int bidx = 0;
    for (int g = 0; g < Gn; g++) {
        float gx1 = s_gx1[g], gy1 = s_gy1[g], gx2 = s_gx2[g], gy2 = s_gy2[g];
        float ix1 = fmaxf(x1, gx1), iy1 = fmaxf(y1, gy1);
        float ix2 = fminf(x2, gx2), iy2 = fminf(y2, gy2);
        float iw = fmaxf(ix2 - ix1, 0.f), ih = fmaxf(iy2 - iy1, 0.f);
        float inter = iw * ih;
        float uni = areaA + s_areaB[g] - inter;
        float iou = inter / uni;
        float ex1 = fminf(x1, gx1), ey1 = fminf(y1, gy1);
        float ex2 = fmaxf(x2, gx2), ey2 = fmaxf(y2, gy2);
        float ew = fmaxf(ex2 - ex1, 0.f), eh = fmaxf(ey2 - ey1, 0.f);
        float areaC = ew * eh;
        float giou = iou - (areaC - uni) / areaC;

        bool ib = (cx > gx1) && (cx < gx2) && (cy > gy1) && (cy < gy2);
        bool icf = (cx > s_bl[g]) && (cx < s_br[g]) && (cy > s_bt[g]) && (cy < s_bb[g]);
        bool inbc = ib && icf;

        float p = lr[s_cls[g]];
        float pos = 0.25f * (1.f - p) * (1.f - p) * (-logf(p + 1e-8f));
        float neg = 0.75f * p * p * (-logf(1.f - p + 1e-8f));
        float ccost = pos - neg;

        float cb = fabsf(nx1 - s_t0[g]) + fabsf(ny1 - s_t1[g]) +
                   fabsf(nx2 - s_t2[g]) + fabsf(ny2 - s_t3[g]);

        float cost = 5.f * cb + 2.f * ccost + 2.f * (-giou) + (inbc ? 0.f : 100.f) + fgpen;
        costOut[(size_t)g * Qn + q] = cost;
        iouOut [(size_t)g * Qn + q] = iou;
        if (cost < best) { best = cost; bidx = g; }
    }
    g_gmin[b * Qn + q] = bidx;
}

// ---------------------------------------------------------------------------
// Stage Sel: one WARP per (b,g); barrier-free register shortlist + merge
// ---------------------------------------------------------------------------
__device__ __forceinline__ unsigned long long warpMinBfly(unsigned long long v) {
    for (int off = 16; off; off >>= 1) {
        unsigned long long o = __shfl_xor_sync(0xffffffffu, v, off);
        if (o < v) v = o;
    }
    return v;
}

#define INS5(k) if ((k) < a4) { a4 = (k); \
    if (a4 < a3) { unsigned long long t = a3; a3 = a4; a4 = t; } \
    if (a3 < a2) { unsigned long long t = a2; a2 = a3; a3 = t; } \
    if (a2 < a1) { unsigned long long t = a1; a1 = a2; a2 = t; } \
    if (a1 < a0) { unsigned long long t = a0; a0 = a1; a1 = t; } }

#define INS8(k) if ((k) < c7) { c7 = (k); \
    if (c7 < c6) { unsigned long long t = c6; c6 = c7; c7 = t; } \
    if (c6 < c5) { unsigned long long t = c5; c5 = c6; c6 = t; } \
    if (c5 < c4) { unsigned long long t = c4; c4 = c5; c5 = t; } \
    if (c4 < c3) { unsigned long long t = c3; c3 = c4; c4 = t; } \
    if (c3 < c2) { unsigned long long t = c2; c2 = c3; c3 = t; } \
    if (c2 < c1) { unsigned long long t = c1; c1 = c2; c2 = t; } \
    if (c1 < c0) { unsigned long long t = c0; c0 = c1; c1 = t; } }

__global__ __launch_bounds__(256) void stageSel()
{
    int task = blockIdx.x * 8 + (threadIdx.x >> 5);    // b*Gn + g
    int lane = threadIdx.x & 31;
    const unsigned long long SENT = ~0ull;

    const float* ic = g_iouT  + (size_t)task * Qn;
    const float* cc = g_costT + (size_t)task * Qn;

    unsigned long long a0 = SENT, a1 = SENT, a2 = SENT, a3 = SENT, a4 = SENT;          // top-5 iou
    unsigned long long c0 = SENT, c1 = SENT, c2 = SENT, c3 = SENT,
                       c4 = SENT, c5 = SENT, c6 = SENT, c7 = SENT;                     // bottom-8 cost

    for (int q = lane; q < Qn; q += 32) {
        unsigned long long ki = ((unsigned long long)(~ordf(ic[q])) << 32) | (unsigned)q;
        INS5(ki);
        unsigned long long kc = ((unsigned long long)ordf(cc[q]) << 32) | (unsigned)q;
        INS8(kc);
    }

    // merge top-5 iou (descending values), sum in extraction order (== jax top_k)
    float sum = 0.f;
    for (int p = 0; p < 5; p++) {
        unsigned long long m = warpMinBfly(a0);
        sum += unordf(~(unsigned int)(m >> 32));
        if (a0 == m) { a0 = a1; a1 = a2; a2 = a3; a3 = a4; a4 = SENT; }
    }
    int k = (int)sum;          // truncating cast, as in the reference
    if (k < 1) k = 1;
    if (k > 5) k = 5;
    if (lane == 0) g_selk[task] = k;

    // merge bottom-8 costs; exact (value, first-index) order
    for (int p = 0; p < LISTN; p++) {
        unsigned long long m = warpMinBfly(c0);
        if (lane == 0) g_list[task * LISTN + p] = (int)(unsigned int)(m & 0xffffffffu);
        if (c0 == m) { c0 = c1; c1 = c2; c2 = c3; c3 = c4; c4 = c5; c5 = c6; c6 = c7; c7 = SENT; }
    }
}

// ---------------------------------------------------------------------------
// Stage B2: one block per image; dedup + bounded refinement via sorted lists
// ---------------------------------------------------------------------------
__device__ __forceinline__ void warpArgMinB(float& v, int& i) {
    for (int off = 16; off; off >>= 1) {
        float ov = __shfl_down_sync(0xffffffffu, v, off);
        int   oi = __shfl_down_sync(0xffffffffu, i, off);
        if (ov < v || (ov == v && oi < i)) { v = ov; i = oi; }
    }
    v = __shfl_sync(0xffffffffu, v, 0);
    i = __shfl_sync(0xffffffffu, i, 0);
}

__device__ __forceinline__ unsigned long long blockMinU64(
    unsigned long long v, unsigned long long* s_w, unsigned long long* s_best,
    int lane, int wid, int nw)
{
    for (int off = 16; off; off >>= 1) {
        unsigned long long o = __shfl_down_sync(0xffffffffu, v, off);
        if (o < v) v = o;
    }
    if (lane == 0) s_w[wid] = v;
    __syncthreads();
    if (threadIdx.x == 0) {
        unsigned long long bb = s_w[0];
        for (int w = 1; w < nw; w++) if (s_w[w] < bb) bb = s_w[w];
        *s_best = bb;
    }
    __syncthreads();
    return *s_best;
}

__global__ __launch_bounds__(512) void stageB2(float* __restrict__ out)
{
    int b = blockIdx.x;
    int tid = threadIdx.x, lane = tid & 31, wid = tid >> 5;   // 16 warps

    __shared__ unsigned long long s_match[Qn];
    __shared__ int                s_penk[Qn];
    __shared__ unsigned long long s_or;
    __shared__ unsigned long long s_fb;
    __shared__ unsigned long long s_w2[16];
    __shared__ unsigned long long s_best2;

    const float* costB = g_costT + (size_t)b * Gn * Qn;
    const int*   gminB = g_gmin  + b * Qn;

    for (int q = tid; q < Qn; q += 512) { s_penk[q] = 0; s_match[q] = 0ull; }
    __syncthreads();

    if (tid < Gn) {
        int bg = b * Gn + tid;
        int k = g_selk[bg];
        for (int p = 0; p < k; p++)
            atomicOr(&s_match[g_list[bg * LISTN + p]], 1ull << tid);
    }
    __syncthreads();

    for (int q = tid; q < Qn; q += 512) {
        unsigned long long m = s_match[q];
        if (__popcll(m) > 1) s_match[q] = 1ull << gminB[q];
    }
    __syncthreads();

    for (int iter = 0; iter < Gn; iter++) {
        if (tid == 0) { s_or = 0ull; s_fb = 0ull; }
        __syncthreads();
        unsigned long long loc = 0ull;
        for (int q = tid; q < Qn; q += 512) loc |= s_match[q];
        for (int off = 16; off; off >>= 1) loc |= __shfl_down_sync(0xffffffffu, loc, off);
        if (lane == 0) atomicOr(&s_or, loc);
        __syncthreads();
        unsigned long long unm = ~s_or;
        if (unm == 0ull) break;

        for (int q = tid; q < Qn; q += 512)
            if (s_match[q] != 0ull) s_penk[q]++;
        __syncthreads();

        // each unmatched gt takes first never-penalized entry in its sorted list
        // (cost < 2e4 < 1e5 => ref argmin over cost+pen is among penk==0 rows)
        if (tid < Gn && ((unm >> tid) & 1ull)) {
            int bg = b * Gn + tid;
            bool found = false;
            for (int p = 0; p < LISTN; p++) {
                int q = g_list[bg * LISTN + p];
                if (s_penk[q] == 0) {
                    atomicOr(&s_match[q], 1ull << tid);
                    found = true;
                    break;
                }
            }
            if (!found) atomicOr(&s_fb, 1ull << tid);
        }
        __syncthreads();

        // exact fallback: full argmin with sequentially-accumulated fp32 penalties
        unsigned long long fb = s_fb;
        while (fb) {
            int g = __ffsll((long long)fb) - 1;
            fb &= fb - 1;
            const float* cg = costB + (size_t)g * Qn;
            unsigned long long bk = ~0ull;
            for (int q = tid; q < Qn; q += 512) {
                float v = cg[q];
                int k = s_penk[q];
                for (int i = 0; i < k; i++) v += 1e5f;    // replicate ref rounding
                unsigned long long key = ((unsigned long long)ordf(v) << 32) | (unsigned)q;
                if (key < bk) bk = key;
            }
            unsigned long long best = blockMinU64(bk, s_w2, &s_best2, lane, wid, 16);
            if (tid == 0) s_match[(unsigned int)(best & 0xffffffffu)] |= 1ull << g;
            __syncthreads();
        }

        for (int q = tid; q < Qn; q += 512) {
            unsigned long long m = s_match[q];
            if (__popcll(m) > 1) s_match[q] = 1ull << gminB[q];
        }
        __syncthreads();
    }

    for (int q = tid; q < Qn; q += 512) g_match[b * Qn + q] = s_match[q];

    float* outI = out + (size_t)Bn * Qn * Gn + (size_t)b * Gn;
    for (int j = 0; j < 4; j++) {
        int g = (wid << 2) + j;
        const float* cc = costB + (size_t)g * Qn;
        float bv = 3.4e38f; int bi = 0x7fffffff;
        for (int q = lane; q < Qn; q += 32) {
            if ((s_match[q] >> g) & 1ull) {
                float v = cc[q];
                int k = s_penk[q];
                for (int i = 0; i < k; i++) v += 1e5f;
                if (v < bv || (v == bv && q < bi)) { bv = v; bi = q; }
            }
        }
        warpArgMinB(bv, bi);
        if (lane == 0) outI[g] = (bi == 0x7fffffff) ? 0.f : (float)bi;
    }
}

// ---------------------------------------------------------------------------
// Stage Out: expand bitmask to [B,Q,G] float matrix, float4 stores
// ---------------------------------------------------------------------------
__global__ __launch_bounds__(256) void stageOut(float* __restrict__ out)
{
    int idx = blockIdx.x * 256 + threadIdx.x;
    int i = idx * 4;
    int b = i / (Qn * Gn);
    int r = i - b * (Qn * Gn);
    int q = r >> 6, g = r & 63;
    unsigned long long m = g_match[b * Qn + q] >> g;
    float4 v;
    v.x = (m & 1ull) ? 1.f : 0.f;
    v.y = (m & 2ull) ? 1.f : 0.f;
    v.z = (m & 4ull) ? 1.f : 0.f;
    v.w = (m & 8ull) ? 1.f : 0.f;
    *reinterpret_cast<float4*>(out + i) = v;
}

// ---------------------------------------------------------------------------
extern "C" void kernel_launch(void* const* d_in, const int* in_sizes, int n_in,
                              void* d_out, int out_size)
{
    const float* logits = (const float*)d_in[0];
    const float* boxes  = (const float*)d_in[1];
    const int*   gtc    = (const int*)  d_in[2];
    const float* gtb    = (const float*)d_in[3];
    const float* szo    = (const float*)d_in[4];
    const float* szt    = (const float*)d_in[5];

    dim3 gA(Bn, (Qn + 127) / 128);
    stageA<<<gA, 128>>>(logits, boxes, gtc, gtb, szo, szt);
    stageSel<<<Bn * Gn / 8, 256>>>();
    stageB2<<<Bn, 512>>>((float*)d_out);
    stageOut<<<(Bn * Qn * Gn / 4) / 256, 256>>>((float*)d_out);
}

// round 10
// speedup vs baseline: 1.0786x; 1.0786x over previous
#include <cuda_runtime.h>
#include <math.h>

#define Bn 32
#define Qn 2000
#define Gn 64
#define Cn 80
#define LISTN 16

// Scratch
__device__ float g_costT[Bn * Gn * Qn];            // [b][g][q]
__device__ float g_iouT [Bn * Gn * Qn];            // [b][g][q]
__device__ int   g_gmin [Bn * Qn];                 // first argmin over g of cost row
__device__ int   g_list [Bn * Gn * LISTN];         // per-gt smallest-cost q ids, sorted; -1 = unknown tail
__device__ int   g_selk [Bn * Gn];                 // dynamic k per gt
__device__ unsigned long long g_match[Bn * Qn];    // final match bitmask per query

// ordered-float transforms (ascending order preserving)
__device__ __forceinline__ unsigned int ordf(float f) {
    unsigned int u = __float_as_uint(f);
    return (u & 0x80000000u) ? ~u : (u | 0x80000000u);
}
__device__ __forceinline__ float unordf(unsigned int o) {
    unsigned int u = (o & 0x80000000u) ? (o ^ 0x80000000u) : ~o;
    return __uint_as_float(u);
}

// ---------------------------------------------------------------------------
// Stage A: pairwise cost + iou + row argmin.
// Per-g invariants hoisted; g iterated in class-sorted order so the focal-loss
// logs are computed once per distinct class (branch uniform across the warp).
// Explicit (cost, g) tie-break makes iteration order irrelevant.
// ---------------------------------------------------------------------------
__global__ __launch_bounds__(128) void stageA(
        const float* __restrict__ logits,   // [B,Q,C]
        const float* __restrict__ boxes,    // [B,Q,4]
        const int*   __restrict__ gtcls,    // [B,G]
        const float* __restrict__ gtbox,    // [B,G,4]
        const float* __restrict__ szout,    // [B,4]
        const float* __restrict__ sztgt)    // [B,G,4]
{
    int b = blockIdx.x;

    __shared__ float s_gx1[Gn], s_gy1[Gn], s_gx2[Gn], s_gy2[Gn];
    __shared__ float s_areaB[Gn];
    __shared__ float s_bl[Gn], s_br[Gn], s_bt[Gn], s_bb[Gn];
    __shared__ float s_t0[Gn], s_t1[Gn], s_t2[Gn], s_t3[Gn];
    __shared__ int   s_cls[Gn];
    __shared__ int   s_ord[Gn];

    if (threadIdx.x < Gn) {
        int g = threadIdx.x;
        const float* gb = gtbox + (size_t)(b * Gn + g) * 4;
        float gx1 = gb[0], gy1 = gb[1], gx2 = gb[2], gy2 = gb[3];
        s_gx1[g] = gx1; s_gy1[g] = gy1; s_gx2[g] = gx2; s_gy2[g] = gy2;
        s_areaB[g] = (gx2 - gx1) * (gy2 - gy1);
        float gcx = (gx1 + gx2) * 0.5f, gcy = (gy1 + gy2) * 0.5f;
        float gw = gx2 - gx1, gh = gy2 - gy1;
        s_bl[g] = gcx - 2.5f * gw; s_br[g] = gcx + 2.5f * gw;
        s_bt[g] = gcy - 2.5f * gh; s_bb[g] = gcy + 2.5f * gh;
        const float* tz = sztgt + (size_t)(b * Gn + g) * 4;
        s_t0[g] = gx1 / tz[0]; s_t1[g] = gy1 / tz[1];
        s_t2[g] = gx2 / tz[2]; s_t3[g] = gy2 / tz[3];
        s_cls[g] = gtcls[b * Gn + g];
    }
    __syncthreads();
    if (threadIdx.x < Gn) {
        int g = threadIdx.x;
        int c = s_cls[g];
        int rank = 0;
        for (int g2 = 0; g2 < Gn; g2++) {
            int c2 = s_cls[g2];
            rank += (c2 < c) || (c2 == c && g2 < g);
        }
        s_ord[rank] = g;
    }
    __syncthreads();

    int q = blockIdx.y * blockDim.x + threadIdx.x;
    if (q >= Qn) return;

    const float* bp = boxes + (size_t)(b * Qn + q) * 4;
    float x1 = bp[0], y1 = bp[1], x2 = bp[2], y2 = bp[3];
    float cx = (x1 + x2) * 0.5f, cy = (y1 + y2) * 0.5f;
    float areaA = (x2 - x1) * (y2 - y1);

    bool anyIB = false, anyIC = false;
    for (int g = 0; g < Gn; g++) {
        bool ib = (cx > s_gx1[g]) && (cx < s_gx2[g]) && (cy > s_gy1[g]) && (cy < s_gy2[g]);
        bool icf = (cx > s_bl[g]) && (cx < s_br[g]) && (cy > s_bt[g]) && (cy < s_bb[g]);
        anyIB |= ib; anyIC |= icf;
    }
    float fgpen = (anyIB || anyIC) ? 0.f : 1e4f;

    float so0 = szout[b * 4], so1 = szout[b * 4 + 1], so2 = szout[b * 4 + 2], so3 = szout[b * 4 + 3];
    float nx1 = x1 / so0, ny1 = y1 / so1, nx2 = x2 / so2, ny2 = y2 / so3;
    const float* lr = logits + (size_t)(b * Qn + q) * Cn;

    float* costOut = g_costT + (size_t)b * Gn * Qn;
    float* iouOut  = g_iouT  + (size_t)b * Gn * Qn;

    float best = 3.4e38f; int bidx = 0x7fffffff;
    int prevc = -1;
    float ccost = 0.f;
    for (int idx = 0; idx < Gn; idx++) {
        int g = s_ord[idx];
        int c = s_cls[g];
        if (c != prevc) {           // uniform across warp (same image, same order)
            float p = lr[c];
            float pos = 0.25f * (1.f - p) * (1.f - p) * (-__logf(p + 1e-8f));
            float neg = 0.75f * p * p * (-__logf(1.f - p + 1e-8f));
            ccost = pos - neg;
            prevc = c;
        }

        float gx1 = s_gx1[g], gy1 = s_gy1[g], gx2 = s_gx2[g], gy2 = s_gy2[g];
        float ix1 = fmaxf(x1, gx1), iy1 = fmaxf(y1, gy1);
        float ix2 = fminf(x2, gx2), iy2 = fminf(y2, gy2);
        float iw = fmaxf(ix2 - ix1, 0.f), ih = fmaxf(iy2 - iy1, 0.f);
        float inter = iw * ih;
        float uni = areaA + s_areaB[g] - inter;
        float iou = inter / uni;                    // exact: feeds floor(top5 sum)
        float ex1 = fminf(x1, gx1), ey1 = fminf(y1, gy1);
        float ex2 = fmaxf(x2, gx2), ey2 = fmaxf(y2, gy2);
        float ew = fmaxf(ex2 - ex1, 0.f), eh = fmaxf(ey2 - ey1, 0.f);
        float areaC = ew * eh;
        float giou = iou - __fdividef(areaC - uni, areaC);   // cost-only

        bool ib = (cx > gx1) && (cx < gx2) && (cy > gy1) && (cy < gy2);
        bool icf = (cx > s_bl[g]) && (cx < s_br[g]) && (cy > s_bt[g]) && (cy < s_bb[g]);
        bool inbc = ib && icf;

        float cb = fabsf(nx1 - s_t0[g]) + fabsf(ny1 - s_t1[g]) +
                   fabsf(nx2 - s_t2[g]) + fabsf(ny2 - s_t3[g]);

        float cost = 5.f * cb + 2.f * ccost + 2.f * (-giou) + (inbc ? 0.f : 100.f) + fgpen;
        costOut[(size_t)g * Qn + q] = cost;
        iouOut [(size_t)g * Qn + q] = iou;
        if (cost < best || (cost == best && g < bidx)) { best = cost; bidx = g; }
    }
    g_gmin[b * Qn + q] = bidx;
}

// ---------------------------------------------------------------------------
// Stage Sel: one WARP per (b,g); barrier-free register shortlist + merge
// ---------------------------------------------------------------------------
__device__ __forceinline__ unsigned long long warpMinBfly(unsigned long long v) {
    for (int off = 16; off; off >>= 1) {
        unsigned long long o = __shfl_xor_sync(0xffffffffu, v, off);
        if (o < v) v = o;
    }
    return v;
}

#define INS5(k) if ((k) < a4) { a4 = (k); \
    if (a4 < a3) { unsigned long long t = a3; a3 = a4; a4 = t; } \
    if (a3 < a2) { unsigned long long t = a2; a2 = a3; a3 = t; } \
    if (a2 < a1) { unsigned long long t = a1; a1 = a2; a2 = t; } \
    if (a1 < a0) { unsigned long long t = a0; a0 = a1; a1 = t; } }

#define INS8(k) if ((k) < c7) { c7 = (k); \
    if (c7 < c6) { unsigned long long t = c6; c6 = c7; c7 = t; } \
    if (c6 < c5) { unsigned long long t = c5; c5 = c6; c6 = t; } \
    if (c5 < c4) { unsigned long long t = c4; c4 = c5; c5 = t; } \
    if (c4 < c3) { unsigned long long t = c3; c3 = c4; c4 = t; } \
    if (c3 < c2) { unsigned long long t = c2; c2 = c3; c3 = t; } \
    if (c2 < c1) { unsigned long long t = c1; c1 = c2; c2 = t; } \
    if (c1 < c0) { unsigned long long t = c0; c0 = c1; c1 = t; } }

__global__ __launch_bounds__(256) void stageSel()
{
    int task = blockIdx.x * 8 + (threadIdx.x >> 5);    // b*Gn + g
    int lane = threadIdx.x & 31;
    const unsigned long long SENT = ~0ull;

    const float* ic = g_iouT  + (size_t)task * Qn;
    const float* cc = g_costT + (size_t)task * Qn;

    unsigned long long a0 = SENT, a1 = SENT, a2 = SENT, a3 = SENT, a4 = SENT;      // top-5 iou
    unsigned long long c0 = SENT, c1 = SENT, c2 = SENT, c3 = SENT,
                       c4 = SENT, c5 = SENT, c6 = SENT, c7 = SENT;                 // bottom-8 cost

    for (int q = lane; q < Qn; q += 32) {
        unsigned long long ki = ((unsigned long long)(~ordf(ic[q])) << 32) | (unsigned)q;
        INS5(ki);
        unsigned long long kc = ((unsigned long long)ordf(cc[q]) << 32) | (unsigned)q;
        INS8(kc);
    }

    // top-5 iou (descending), summed in extraction order (== jax top_k)
    float sum = 0.f;
    for (int p = 0; p < 5; p++) {
        unsigned long long m = warpMinBfly(a0);
        sum += unordf(~(unsigned int)(m >> 32));
        if (a0 == m) { a0 = a1; a1 = a2; a2 = a3; a3 = a4; a4 = SENT; }
    }
    int k = (int)sum;          // truncating cast, as in the reference
    if (k < 1) k = 1;
    if (k > 5) k = 5;
    if (lane == 0) g_selk[task] = k;

    // bottom-16 costs from per-lane bottom-8 runs. Exact unless some lane
    // exhausts all 8 entries mid-merge (astronomically rare); from that point
    // entries are unknown -> emit -1 (stageB2 falls back to an exact scan).
    int ptr = 0;
    bool bad = false;
    for (int p = 0; p < LISTN; p++) {
        bad |= (__any_sync(0xffffffffu, ptr == 8) != 0);
        unsigned long long m = warpMinBfly(c0);
        if (lane == 0) g_list[task * LISTN + p] = bad ? -1 : (int)(unsigned int)(m & 0xffffffffu);
        if (!bad && c0 == m) {
            c0 = c1; c1 = c2; c2 = c3; c3 = c4; c4 = c5; c5 = c6; c6 = c7; c7 = SENT;
            ptr++;
        }
    }
}

// ---------------------------------------------------------------------------
// Stage B2: one block per image; dedup + bounded refinement via sorted lists
// ---------------------------------------------------------------------------
__device__ __forceinline__ void warpArgMinB(float& v, int& i) {
    for (int off = 16; off; off >>= 1) {
        float ov = __shfl_down_sync(0xffffffffu, v, off);
        int   oi = __shfl_down_sync(0xffffffffu, i, off);
        if (ov < v || (ov == v && oi < i)) { v = ov; i = oi; }
    }
    v = __shfl_sync(0xffffffffu, v, 0);
    i = __shfl_sync(0xffffffffu, i, 0);
}

__device__ __forceinline__ unsigned long long blockMinU64(
    unsigned long long v, unsigned long long* s_w, unsigned long long* s_best,
    int lane, int wid, int nw)
{
    for (int off = 16; off; off >>= 1) {
        unsigned long long o = __shfl_down_sync(0xffffffffu, v, off);
        if (o < v) v = o;
    }
    if (lane == 0) s_w[wid] = v;
    __syncthreads();
    if (threadIdx.x == 0) {
        unsigned long long bb = s_w[0];
        for (int w = 1; w < nw; w++) if (s_w[w] < bb) bb = s_w[w];
        *s_best = bb;
    }
    __syncthreads();
    return *s_best;
}

__global__ __launch_bounds__(512) void stageB2(float* __restrict__ out)
{
    int b = blockIdx.x;
    int tid = threadIdx.x, lane = tid & 31, wid = tid >> 5;   // 16 warps

    __shared__ unsigned long long s_match[Qn];
    __shared__ int                s_penk[Qn];
    __shared__ unsigned long long s_or;
    __shared__ unsigned long long s_fb;
    __shared__ unsigned long long s_w2[16];
    __shared__ unsigned long long s_best2;

    const float* costB = g_costT + (size_t)b * Gn * Qn;
    const int*   gminB = g_gmin  + b * Qn;

    for (int q = tid; q < Qn; q += 512) { s_penk[q] = 0; s_match[q] = 0ull; }
    __syncthreads();

    if (tid < Gn) {
        int bg = b * Gn + tid;
        int k = g_selk[bg];
        for (int p = 0; p < k; p++)
            atomicOr(&s_match[g_list[bg * LISTN + p]], 1ull << tid);
    }
    __syncthreads();

    for (int q = tid; q < Qn; q += 512) {
        unsigned long long m = s_match[q];
        if (__popcll(m) > 1) s_match[q] = 1ull << gminB[q];
    }
    __syncthreads();

    for (int iter = 0; iter < Gn; iter++) {
        if (tid == 0) { s_or = 0ull; s_fb = 0ull; }
        __syncthreads();
        unsigned long long loc = 0ull;
        for (int q = tid; q < Qn; q += 512) loc |= s_match[q];
        for (int off = 16; off; off >>= 1) loc |= __shfl_down_sync(0xffffffffu, loc, off);
        if (lane == 0) atomicOr(&s_or, loc);
        __syncthreads();
        unsigned long long unm = ~s_or;
        if (unm == 0ull) break;

        for (int q = tid; q < Qn; q += 512)
            if (s_match[q] != 0ull) s_penk[q]++;
        __syncthreads();

        // each unmatched gt takes first never-penalized entry in its sorted list
        // (cost < 2e4 < 1e5 => ref argmin over cost+pen is among penk==0 rows)
        if (tid < Gn && ((unm >> tid) & 1ull)) {
            int bg = b * Gn + tid;
            bool found = false;
            for (int p = 0; p < LISTN; p++) {
                int q = g_list[bg * LISTN + p];
                if (q < 0) break;                  // unknown tail -> exact fallback
                if (s_penk[q] == 0) {
                    atomicOr(&s_match[q], 1ull << tid);
                    found = true;
                    break;
                }
            }
            if (!found) atomicOr(&s_fb, 1ull << tid);
        }
        __syncthreads();

        // exact fallback: full argmin with sequentially-accumulated fp32 penalties
        unsigned long long fb = s_fb;
        while (fb) {
            int g = __ffsll((long long)fb) - 1;
            fb &= fb - 1;
            const float* cg = costB + (size_t)g * Qn;
            unsigned long long bk = ~0ull;
            for (int q = tid; q < Qn; q += 512) {
                float v = cg[q];
                int k = s_penk[q];
                for (int i = 0; i < k; i++) v += 1e5f;    // replicate ref rounding
                unsigned long long key = ((unsigned long long)ordf(v) << 32) | (unsigned)q;
                if (key < bk) bk = key;
            }
            unsigned long long best = blockMinU64(bk, s_w2, &s_best2, lane, wid, 16);
            if (tid == 0) s_match[(unsigned int)(best & 0xffffffffu)] |= 1ull << g;
            __syncthreads();
        }

        for (int q = tid; q < Qn; q += 512) {
            unsigned long long m = s_match[q];
            if (__popcll(m) > 1) s_match[q] = 1ull << gminB[q];
        }
        __syncthreads();
    }

    for (int q = tid; q < Qn; q += 512) g_match[b * Qn + q] = s_match[q];

    float* outI = out + (size_t)Bn * Qn * Gn + (size_t)b * Gn;
    for (int j = 0; j < 4; j++) {
        int g = (wid << 2) + j;
        const float* cc = costB + (size_t)g * Qn;
        float bv = 3.4e38f; int bi = 0x7fffffff;
        for (int q = lane; q < Qn; q += 32) {
            if ((s_match[q] >> g) & 1ull) {
                float v = cc[q];
                int k = s_penk[q];
                for (int i = 0; i < k; i++) v += 1e5f;
                if (v < bv || (v == bv && q < bi)) { bv = v; bi = q; }
            }
        }
        warpArgMinB(bv, bi);
        if (lane == 0) outI[g] = (bi == 0x7fffffff) ? 0.f : (float)bi;
    }
}

// ---------------------------------------------------------------------------
// Stage Out: expand bitmask to [B,Q,G] float matrix, float4 stores
// ---------------------------------------------------------------------------
__global__ __launch_bounds__(256) void stageOut(float* __restrict__ out)
{
    int idx = blockIdx.x * 256 + threadIdx.x;
    int i = idx * 4;
    int b = i / (Qn * Gn);
    int r = i - b * (Qn * Gn);
    int q = r >> 6, g = r & 63;
    unsigned long long m = g_match[b * Qn + q] >> g;
    float4 v;
    v.x = (m & 1ull) ? 1.f : 0.f;
    v.y = (m & 2ull) ? 1.f : 0.f;
    v.z = (m & 4ull) ? 1.f : 0.f;
    v.w = (m & 8ull) ? 1.f : 0.f;
    *reinterpret_cast<float4*>(out + i) = v;
}

// ---------------------------------------------------------------------------
extern "C" void kernel_launch(void* const* d_in, const int* in_sizes, int n_in,
                              void* d_out, int out_size)
{
    const float* logits = (const float*)d_in[0];
    const float* boxes  = (const float*)d_in[1];
    const int*   gtc    = (const int*)  d_in[2];
    const float* gtb    = (const float*)d_in[3];
    const float* szo    = (const float*)d_in[4];
    const float* szt    = (const float*)d_in[5];

    dim3 gA(Bn, (Qn + 127) / 128);
    stageA<<<gA, 128>>>(logits, boxes, gtc, gtb, szo, szt);
    stageSel<<<Bn * Gn / 8, 256>>>();
    stageB2<<<Bn, 512>>>((float*)d_out);
    stageOut<<<(Bn * Qn * Gn / 4) / 256, 256>>>((float*)d_out);
}